// round 14
// baseline (speedup 1.0000x reference)
#include <cuda_runtime.h>
#include <math.h>

// Problem constants (shapes fixed by the dataset)
#define NN      50000
#define EEMAX   800000
#define ETMAX   850000   // edges + self loops
#define INC     128

// ---------------- scratch (static __device__; no allocs allowed) ----------------
__device__ float g_h  [NN * 128];   // per-layer projected features (pre-aggregation)
__device__ float g_o1 [NN * 128];   // layer1 output
__device__ float g_o2 [NN * 64];    // layer2 output
__device__ float g_as [NN * 4];     // alpha_src per node per head
__device__ float g_ad [NN * 4];     // alpha_dst per node per head
__device__ float g_wa [2048];       // folded alpha weights: L1 @0 (2*4*128), L2 @1024 (2*2*128), L3 @1536 (2*1*64)
__device__ int   g_srcA[ETMAX];
__device__ int   g_dstA[ETMAX];
__device__ int   g_ssrc[ETMAX];     // src sorted by dst
__device__ int   g_deg [NN];
__device__ int   g_startA[NN + 1];
__device__ int   g_cursor[NN];
__device__ int   g_bsum[128];
__device__ int   g_is64;

// ---------------- helpers ----------------
__device__ __forceinline__ float leaky(float x) {
    return x >= 0.f ? x : 0.2f * x;
}

__device__ __forceinline__ unsigned long long pack2(float x) {
    unsigned long long r;
    asm("mov.b64 %0, {%1, %1};" : "=l"(r) : "r"(__float_as_uint(x)));
    return r;
}
__device__ __forceinline__ void ffma2(unsigned long long& d,
                                      unsigned long long a, unsigned long long b) {
    asm("fma.rn.f32x2 %0, %1, %2, %0;" : "+l"(d) : "l"(a), "l"(b));
}
__device__ __forceinline__ float lo32(unsigned long long u) {
    return __uint_as_float((unsigned)(u & 0xffffffffu));
}
__device__ __forceinline__ float hi32(unsigned long long u) {
    return __uint_as_float((unsigned)(u >> 32));
}

template<int H>
__device__ __forceinline__ void loadH(const float* __restrict__ p, float* a) {
    if (H == 4) {
        float4 v = *reinterpret_cast<const float4*>(p);
        a[0] = v.x; a[1] = v.y; a[2] = v.z; a[3] = v.w;
    } else if (H == 2) {
        float2 v = *reinterpret_cast<const float2*>(p);
        a[0] = v.x; a[1] = v.y;
    } else {
        a[0] = p[0];
    }
}

// ---------------- edge preprocessing ----------------
__global__ void k_zero(int n) {
    int i = blockIdx.x * blockDim.x + threadIdx.x;
    if (i < n) { g_deg[i] = 0; g_cursor[i] = 0; }
}

// Detect whether edge_index buffer is int64 (odd 32-bit words ~all zero) or int32.
__global__ void k_detect(const int* __restrict__ p) {
    if (blockIdx.x == 0 && threadIdx.x == 0) {
        int z = 0;
        for (int i = 0; i < 256; i++) if (p[2 * i + 1] == 0) z++;
        g_is64 = (z > 200) ? 1 : 0;
    }
}

__global__ void k_extract(const void* __restrict__ ei, int E, int ET) {
    int i = blockIdx.x * blockDim.x + threadIdx.x;
    if (i >= ET) return;
    int s, d;
    if (i < E) {
        if (g_is64) {
            const long long* p = (const long long*)ei;
            s = (int)p[i]; d = (int)p[(long long)E + i];
        } else {
            const int* p = (const int*)ei;
            s = p[i]; d = p[E + i];
        }
    } else {
        s = d = i - E;   // self loop
    }
    g_srcA[i] = s; g_dstA[i] = d;
    atomicAdd(&g_deg[d], 1);
}

// -------- multi-block exclusive scan: deg -> startA --------
__global__ void k_scan1(int n) {
    __shared__ int wsum[32];
    int t = threadIdx.x;
    int i = blockIdx.x * 1024 + t;
    int v = (i < n) ? g_deg[i] : 0;
    int lane = t & 31, w = t >> 5;
    int x = v;
    #pragma unroll
    for (int d = 1; d < 32; d <<= 1) {
        int y = __shfl_up_sync(0xffffffffu, x, d);
        if (lane >= d) x += y;
    }
    if (lane == 31) wsum[w] = x;
    __syncthreads();
    if (w == 0) {
        int s = wsum[lane];
        #pragma unroll
        for (int d = 1; d < 32; d <<= 1) {
            int y = __shfl_up_sync(0xffffffffu, s, d);
            if (lane >= d) s += y;
        }
        wsum[lane] = s;
    }
    __syncthreads();
    int excl = x - v + (w > 0 ? wsum[w - 1] : 0);
    if (i < n) g_startA[i] = excl;
    if (t == 1023) g_bsum[blockIdx.x] = excl + v;
}

__global__ void k_scan2(int nb, int n) {
    if (threadIdx.x == 0) {
        int run = 0;
        for (int b = 0; b < nb; b++) {
            int v = g_bsum[b];
            g_bsum[b] = run;
            run += v;
        }
        g_startA[n] = run;
    }
}

__global__ void k_scan3(int n) {
    int i = blockIdx.x * 1024 + threadIdx.x;
    if (i < n) g_startA[i] += g_bsum[blockIdx.x];
}

__global__ void k_scatter(int ET) {
    int i = blockIdx.x * blockDim.x + threadIdx.x;
    if (i >= ET) return;
    int d = g_dstA[i];
    int pos = g_startA[d] + atomicAdd(&g_cursor[d], 1);
    g_ssrc[pos] = g_srcA[i];
}

// ---------------- fold alpha vectors through W: wa[h][k] = sum_c W[k, h*C+c]*a[h,c] ----------------
__global__ void k_fold(const float* __restrict__ W, const float* __restrict__ asrc,
                       const float* __restrict__ adst, float* __restrict__ wa,
                       int K_, int H_, int C_) {
    int k = blockIdx.x * blockDim.x + threadIdx.x;
    if (k >= K_) return;
    for (int h = 0; h < H_; h++) {
        float ss = 0.f, sd = 0.f;
        for (int c = 0; c < C_; c++) {
            float w = W[k * (H_ * C_) + h * C_ + c];
            ss += w * asrc[h * C_ + c];
            sd += w * adst[h * C_ + c];
        }
        wa[h * K_ + k]        = ss;   // src rows [0..H)
        wa[(H_ + h) * K_ + k] = sd;   // dst rows [H..2H)
    }
}

// ---------------- alpha from layer INPUT via folded weights: AS/AD = Xin @ wa^T ----------------
template<int K, int H>
__global__ void k_alphaF(const float* __restrict__ X, const float* __restrict__ wa,
                         float* __restrict__ AS, float* __restrict__ AD, int n) {
    int i = blockIdx.x * blockDim.x + threadIdx.x;
    if (i >= n) return;
    float sa[H], sd[H];
    #pragma unroll
    for (int h = 0; h < H; h++) { sa[h] = 0.f; sd[h] = 0.f; }
    const float4* row = reinterpret_cast<const float4*>(X + (long long)i * K);
    #pragma unroll
    for (int q = 0; q < K / 4; q++) {
        float4 v = row[q];
        #pragma unroll
        for (int h = 0; h < H; h++) {
            float4 ws_ = reinterpret_cast<const float4*>(wa + h * K)[q];
            float4 wd_ = reinterpret_cast<const float4*>(wa + (H + h) * K)[q];
            sa[h] += v.x * ws_.x + v.y * ws_.y + v.z * ws_.z + v.w * ws_.w;
            sd[h] += v.x * wd_.x + v.y * wd_.y + v.z * wd_.z + v.w * wd_.w;
        }
    }
    #pragma unroll
    for (int h = 0; h < H; h++) {
        AS[i * H + h] = sa[h];
        AD[i * H + h] = sd[h];
    }
}

// ---------------- dense projection GEMM: Hout[n, NOUT] = X[n, K] @ W[K, NOUT] ----------------
// BM=128, BK=32; 256 threads; TN>=4 uses packed fma.rn.f32x2 (pairs along N).
template<int K, int NOUT>
__global__ void __launch_bounds__(256, 2)
k_gemm(const float* __restrict__ X, const float* __restrict__ W,
       float* __restrict__ Hout, int n) {
    constexpr int BM = 128, BK = 32;
    constexpr int TM = 8, TN = NOUT / 16;
    constexpr int NP = (TN >= 4) ? TN / 2 : 1;   // f32x2 pairs along N
    __shared__ float xs[BK][BM];       // transposed A tile: xs[k][row]
    __shared__ float ws[BK][NOUT];

    int t  = threadIdx.x;
    int tx = t % 16, ty = t / 16;
    int row0 = blockIdx.x * BM;

    unsigned long long accp[TM][NP];
    float accs[TM];                    // scalar path (TN==1)
    #pragma unroll
    for (int i = 0; i < TM; i++) {
        accs[i] = 0.f;
        #pragma unroll
        for (int j = 0; j < NP; j++) accp[i][j] = 0ull;
    }

    for (int k0 = 0; k0 < K; k0 += BK) {
        #pragma unroll
        for (int i = 0; i < (BM * BK / 4) / 256; i++) {
            int id  = t + i * 256;
            int row = id & (BM - 1);
            int kq  = id >> 7;
            float4 v = make_float4(0.f, 0.f, 0.f, 0.f);
            if (row0 + row < n)
                v = *reinterpret_cast<const float4*>(X + (long long)(row0 + row) * K + k0 + kq * 4);
            xs[kq * 4 + 0][row] = v.x;
            xs[kq * 4 + 1][row] = v.y;
            xs[kq * 4 + 2][row] = v.z;
            xs[kq * 4 + 3][row] = v.w;
        }
        for (int i = t; i < BK * NOUT / 4; i += 256) {
            int kk = i / (NOUT / 4);
            int c4 = i % (NOUT / 4);
            float4 v = *reinterpret_cast<const float4*>(W + (long long)(k0 + kk) * NOUT + c4 * 4);
            *reinterpret_cast<float4*>(&ws[kk][c4 * 4]) = v;
        }
        __syncthreads();

        #pragma unroll
        for (int kk = 0; kk < BK; kk++) {
            float a[TM];
            float4 a0 = *reinterpret_cast<const float4*>(&xs[kk][ty * 8]);
            float4 a1 = *reinterpret_cast<const float4*>(&xs[kk][ty * 8 + 4]);
            a[0] = a0.x; a[1] = a0.y; a[2] = a0.z; a[3] = a0.w;
            a[4] = a1.x; a[5] = a1.y; a[6] = a1.z; a[7] = a1.w;
            if (TN >= 4) {
                // b pairs straight from smem (64-bit), a broadcast-packed
                unsigned long long bp[NP];
                const unsigned long long* wq =
                    reinterpret_cast<const unsigned long long*>(&ws[kk][tx * TN]);
                #pragma unroll
                for (int j = 0; j < NP; j++) bp[j] = wq[j];
                unsigned long long ap[TM];
                #pragma unroll
                for (int i = 0; i < TM; i++) ap[i] = pack2(a[i]);
                #pragma unroll
                for (int i = 0; i < TM; i++)
                    #pragma unroll
                    for (int j = 0; j < NP; j++) ffma2(accp[i][j], ap[i], bp[j]);
            } else {
                float b = ws[kk][tx];
                #pragma unroll
                for (int i = 0; i < TM; i++) accs[i] += a[i] * b;
            }
        }
        __syncthreads();
    }

    #pragma unroll
    for (int i = 0; i < TM; i++) {
        int row = row0 + ty * 8 + i;
        if (row < n) {
            float* orow = Hout + (long long)row * NOUT + tx * TN;
            if (TN == 8) {
                float4 v0 = make_float4(lo32(accp[i][0]), hi32(accp[i][0]),
                                        lo32(accp[i][1]), hi32(accp[i][1]));
                float4 v1 = make_float4(lo32(accp[i][2]), hi32(accp[i][2]),
                                        lo32(accp[i][3]), hi32(accp[i][3]));
                *reinterpret_cast<float4*>(orow)     = v0;
                *reinterpret_cast<float4*>(orow + 4) = v1;
            } else if (TN == 4) {
                float4 v0 = make_float4(lo32(accp[i][0]), hi32(accp[i][0]),
                                        lo32(accp[i][1]), hi32(accp[i][1]));
                *reinterpret_cast<float4*>(orow)     = v0;
            } else {
                orow[0] = accs[i];
            }
        }
    }
}

// ---------------- warp-per-node ONE-PASS online softmax + aggregation ----------------
// NG = 32/(HC/4) gather groups per warp; group g handles chunk edges j = g, g+NG, ...
// Running rescale sc is warp-uniform, so per-group partial accs sum correctly at the end.
template<int H, int C, bool RELU>
__global__ void k_agg(const float* __restrict__ Hf, const float* __restrict__ AS,
                      const float* __restrict__ AD, const int* __restrict__ startA,
                      const int* __restrict__ ssrc, const float* __restrict__ bias,
                      float* __restrict__ out, int n) {
    constexpr int HC  = H * C;
    constexpr int GL  = HC / 4;                  // lanes per gather group (float4 each)
    constexpr int NG  = 32 / GL;                 // gather groups per warp
    constexpr int WPB = 8;                       // warps per block
    int warp = threadIdx.x >> 5, lane = threadIdx.x & 31;
    int nd = blockIdx.x * WPB + warp;
    if (nd >= n) return;

    __shared__ float s_w[WPB][H * 33];           // [h*33 + lane]: conflict-free
    __shared__ int   s_s[WPB][32];

    int beg = startA[nd], end = startA[nd + 1];

    float ad[H];
    loadH<H>(AD + nd * H, ad);

    int grp = lane / GL;                         // gather group
    int q   = lane % GL;                         // channel quad within row
    int myhead = (q * 4) / C;                    // per-lane constant
    float m[H], s[H], acc[4];
    #pragma unroll
    for (int h = 0; h < H; h++) { m[h] = -INFINITY; s[h] = 0.f; }
    #pragma unroll
    for (int v = 0; v < 4; v++) acc[v] = 0.f;

    for (int cbeg = beg; cbeg < end; cbeg += 32) {
        int cl = end - cbeg; if (cl > 32) cl = 32;

        float l[H];
        int src = 0;
        if (lane < cl) {
            src = ssrc[cbeg + lane];
            float as[H];
            loadH<H>(AS + src * H, as);
            #pragma unroll
            for (int h = 0; h < H; h++) l[h] = leaky(as[h] + ad[h]);
        } else {
            #pragma unroll
            for (int h = 0; h < H; h++) l[h] = -INFINITY;
        }

        // chunk max (butterfly)
        float cm[H];
        #pragma unroll
        for (int h = 0; h < H; h++) cm[h] = l[h];
        #pragma unroll
        for (int off = 16; off > 0; off >>= 1)
            #pragma unroll
            for (int h = 0; h < H; h++)
                cm[h] = fmaxf(cm[h], __shfl_xor_sync(0xffffffffu, cm[h], off));

        // merge with running max; rescale factors (m=-inf on first chunk -> exp(-inf)=0)
        float nm[H], sc[H], w[H], cs[H];
        #pragma unroll
        for (int h = 0; h < H; h++) {
            nm[h] = fmaxf(m[h], cm[h]);          // finite: cl >= 1
            sc[h] = __expf(m[h] - nm[h]);
            w[h]  = __expf(l[h] - nm[h]);        // lane >= cl: exp(-inf)=0
            cs[h] = w[h];
            m[h]  = nm[h];
        }
        // chunk exp-sum (butterfly)
        #pragma unroll
        for (int off = 16; off > 0; off >>= 1)
            #pragma unroll
            for (int h = 0; h < H; h++)
                cs[h] += __shfl_xor_sync(0xffffffffu, cs[h], off);
        #pragma unroll
        for (int h = 0; h < H; h++) s[h] = s[h] * sc[h] + cs[h];

        if (lane < cl) {
            s_s[warp][lane] = src;
            #pragma unroll
            for (int h = 0; h < H; h++) s_w[warp][h * 33 + lane] = w[h];
        }
        __syncwarp();

        {
            float rs = sc[myhead];
            #pragma unroll
            for (int v = 0; v < 4; v++) acc[v] *= rs;
            const float* base = Hf + (long long)q * 4;
            #pragma unroll 4
            for (int j = grp; j < cl; j += NG) {
                float  wj  = s_w[warp][myhead * 33 + j];
                float4 v   = *reinterpret_cast<const float4*>(base + (long long)s_s[warp][j] * HC);
                acc[0] += wj * v.x; acc[1] += wj * v.y;
                acc[2] += wj * v.z; acc[3] += wj * v.w;
            }
        }
        __syncwarp();
    }

    // sum partial accumulators across gather groups (xor on high lane bits; no-op when NG==1)
    #pragma unroll
    for (int off = GL; off < 32; off <<= 1) {
        #pragma unroll
        for (int v = 0; v < 4; v++)
            acc[v] += __shfl_xor_sync(0xffffffffu, acc[v], off);
    }

    if (lane < GL) {
        float inv = 1.f / (s[myhead] + 1e-16f);
        float4 bv = *reinterpret_cast<const float4*>(bias + lane * 4);
        float4 o;
        o.x = acc[0] * inv + bv.x;
        o.y = acc[1] * inv + bv.y;
        o.z = acc[2] * inv + bv.z;
        o.w = acc[3] * inv + bv.w;
        if (RELU) {
            o.x = fmaxf(o.x, 0.f); o.y = fmaxf(o.y, 0.f);
            o.z = fmaxf(o.z, 0.f); o.w = fmaxf(o.w, 0.f);
        }
        *reinterpret_cast<float4*>(out + (long long)nd * HC + lane * 4) = o;
    }
}

// ---------------- launcher ----------------
extern "C" void kernel_launch(void* const* d_in, const int* in_sizes, int n_in,
                              void* d_out, int out_size) {
    const float* x     = (const float*)d_in[0];
    const void*  ei    = d_in[1];
    const float* W1    = (const float*)d_in[2];
    const float* asr1  = (const float*)d_in[3];
    const float* ads1  = (const float*)d_in[4];
    const float* b1    = (const float*)d_in[5];
    const float* W2    = (const float*)d_in[6];
    const float* asr2  = (const float*)d_in[7];
    const float* ads2  = (const float*)d_in[8];
    const float* b2    = (const float*)d_in[9];
    const float* W3    = (const float*)d_in[10];
    const float* asr3  = (const float*)d_in[11];
    const float* ads3  = (const float*)d_in[12];
    const float* b3    = (const float*)d_in[13];

    int N  = in_sizes[0] / INC;
    int E  = in_sizes[1] / 2;
    int ET = E + N;

    void* p;
    cudaGetSymbolAddress(&p, g_h);      float* d_h   = (float*)p;
    cudaGetSymbolAddress(&p, g_o1);     float* d_o1  = (float*)p;
    cudaGetSymbolAddress(&p, g_o2);     float* d_o2  = (float*)p;
    cudaGetSymbolAddress(&p, g_as);     float* d_as  = (float*)p;
    cudaGetSymbolAddress(&p, g_ad);     float* d_ad  = (float*)p;
    cudaGetSymbolAddress(&p, g_wa);     float* d_wa  = (float*)p;
    cudaGetSymbolAddress(&p, g_startA); int*   d_st  = (int*)p;
    cudaGetSymbolAddress(&p, g_ssrc);   int*   d_ss  = (int*)p;

    float* wa1 = d_wa;          // 2*4*128 = 1024
    float* wa2 = d_wa + 1024;   // 2*2*128 = 512
    float* wa3 = d_wa + 1536;   // 2*1*64  = 128

    // init-once side streams + fork/join events
    static cudaStream_t s1 = nullptr, s2 = nullptr;
    static cudaEvent_t ev[8];
    if (s1 == nullptr) {
        cudaStreamCreateWithFlags(&s1, cudaStreamNonBlocking);
        cudaStreamCreateWithFlags(&s2, cudaStreamNonBlocking);
        for (int i = 0; i < 8; i++)
            cudaEventCreateWithFlags(&ev[i], cudaEventDisableTiming);
    }

    int nb = (N + 1023) / 1024;
    int gB = (N + 127) / 128;
    int gA = (N + 7) / 8;        // 8 warps (nodes) per 256-thread block
    int gN = (N + 127) / 128;

    // ---- fork: preprocessing on s1, alpha1 chain on s2, GEMM1 on main ----
    cudaEventRecord(ev[0], 0);
    cudaStreamWaitEvent(s1, ev[0], 0);
    cudaStreamWaitEvent(s2, ev[0], 0);

    // s1: counting sort of edges by destination
    k_zero   <<<(N  + 255) / 256, 256, 0, s1>>>(N);
    k_detect <<<1, 32, 0, s1>>>((const int*)ei);
    k_extract<<<(ET + 255) / 256, 256, 0, s1>>>(ei, E, ET);
    k_scan1  <<<nb, 1024, 0, s1>>>(N);
    k_scan2  <<<1, 32, 0, s1>>>(nb, N);
    k_scan3  <<<nb, 1024, 0, s1>>>(N);
    k_scatter<<<(ET + 255) / 256, 256, 0, s1>>>(ET);
    cudaEventRecord(ev[1], s1);                    // preprocessing done

    // s2: fold alpha weights (all layers) + alpha1 from x
    k_fold<<<1, 128, 0, s2>>>(W1, asr1, ads1, wa1, 128, 4, 32);
    k_fold<<<1, 128, 0, s2>>>(W2, asr2, ads2, wa2, 128, 2, 32);
    k_fold<<<1, 128, 0, s2>>>(W3, asr3, ads3, wa3, 64, 1, 16);
    k_alphaF<128, 4><<<gN, 128, 0, s2>>>(x, wa1, d_as, d_ad, N);
    cudaEventRecord(ev[2], s2);                    // alpha1 done

    // main: layer-1 projection
    k_gemm<128, 128><<<gB, 256>>>(x, W1, d_h, N);

    // join for agg1: needs edges + alpha1 + gemm1
    cudaStreamWaitEvent(0, ev[1], 0);
    cudaStreamWaitEvent(0, ev[2], 0);
    k_agg<4, 32, true><<<gA, 256>>>(d_h, d_as, d_ad, d_st, d_ss, b1, d_o1, N);

    // ---- layer 2: alpha2 (from o1) on s2 concurrent with gemm2 ----
    cudaEventRecord(ev[3], 0);
    cudaStreamWaitEvent(s2, ev[3], 0);
    k_alphaF<128, 2><<<gN, 128, 0, s2>>>(d_o1, wa2, d_as, d_ad, N);
    cudaEventRecord(ev[4], s2);

    k_gemm<128, 64><<<gB, 256>>>(d_o1, W2, d_h, N);
    cudaStreamWaitEvent(0, ev[4], 0);
    k_agg<2, 32, true><<<gA, 256>>>(d_h, d_as, d_ad, d_st, d_ss, b2, d_o2, N);

    // ---- layer 3: alpha3 (from o2) on s2 concurrent with gemm3 ----
    cudaEventRecord(ev[5], 0);
    cudaStreamWaitEvent(s2, ev[5], 0);
    k_alphaF<64, 1><<<gN, 128, 0, s2>>>(d_o2, wa3, d_as, d_ad, N);
    cudaEventRecord(ev[6], s2);

    k_gemm<64, 16><<<gB, 256>>>(d_o2, W3, d_h, N);
    cudaStreamWaitEvent(0, ev[6], 0);
    k_agg<1, 16, false><<<gA, 256>>>(d_h, d_as, d_ad, d_st, d_ss, b3, (float*)d_out, N);
}